// round 10
// baseline (speedup 1.0000x reference)
#include <cuda_runtime.h>
#include <cstdint>

// GlobalFilter: out = irfft2( rfft2(x,ortho) * W, ortho ), 16x16 spatial, per channel.
//   Ph1: column rDFT over t (radix-2 folded, scalar FFMA-imm)   thread=(c32, 2 rows)
//   Ph2: per-(c,v) row circular conv via 16-pt FFT + pointwise
//        raw-W multiply (regs, x1/128) + IFFT (v=1..7);
//        v={0,8} packed real dense conv (taps in regs)
//   Ph3: inverse column pass (radix-2 folded, scalar)           thread=(c32, 2 rows)
//   Filter state preloaded once per block, amortized over 4 batches.
//
// x: [128,256,768] f32 ; W: [16,9,768,2] f32 ; out: [128,256,768] f32

#define PP    16
#define NV    9
#define CT    32
#define CCH   768
#define NCT   (CCH / CT)   // 24
#define BPB   4            // batches per block

// real taps for v=0 / v=8 dense conv: [ct][d][c32] -> (mu0, mu8) * 1/256
__device__ float2 g_muR[NCT * PP * CT];

__host__ __device__ __forceinline__ constexpr float C16(int k) {
    return (k % 16 == 0)  ?  1.0f :
           (k % 16 == 1)  ?  0.9238795325112867f :
           (k % 16 == 2)  ?  0.7071067811865476f :
           (k % 16 == 3)  ?  0.3826834323650898f :
           (k % 16 == 4)  ?  0.0f :
           (k % 16 == 5)  ? -0.3826834323650898f :
           (k % 16 == 6)  ? -0.7071067811865476f :
           (k % 16 == 7)  ? -0.9238795325112867f :
           (k % 16 == 8)  ? -1.0f :
           (k % 16 == 9)  ? -0.9238795325112867f :
           (k % 16 == 10) ? -0.7071067811865476f :
           (k % 16 == 11) ? -0.3826834323650898f :
           (k % 16 == 12) ?  0.0f :
           (k % 16 == 13) ?  0.3826834323650898f :
           (k % 16 == 14) ?  0.7071067811865476f :
                             0.9238795325112867f;
}
__host__ __device__ __forceinline__ constexpr float S16(int k) {
    return C16(k % 16 + 12);
}
__host__ __device__ __forceinline__ constexpr int REV4(int i) {
    return ((i & 1) << 3) | ((i & 2) << 1) | ((i & 4) >> 1) | ((i & 8) >> 3);
}

// a+b / a-b as FFMA-imm (rt=1 vs rt=2 for FADD)
__device__ __forceinline__ float fadd1(float a, float b) {
    float r; asm("fma.rn.f32 %0, %1, 0f3F800000, %2;" : "=f"(r) : "f"(a), "f"(b)); return r;
}
__device__ __forceinline__ float fsub1(float a, float b) {  // a - b
    float r; asm("fma.rn.f32 %0, %1, 0fBF800000, %2;" : "=f"(r) : "f"(b), "f"(a)); return r;
}

__device__ __forceinline__ uint64_t pack2(float lo, float hi) {
    uint64_t r; asm("mov.b64 %0, {%1, %2};" : "=l"(r) : "f"(lo), "f"(hi)); return r;
}
__device__ __forceinline__ void unpack2(uint64_t v, float& lo, float& hi) {
    asm("mov.b64 {%0, %1}, %2;" : "=f"(lo), "=f"(hi) : "l"(v));
}
__device__ __forceinline__ uint64_t fma2(uint64_t a, uint64_t b, uint64_t c) {
    uint64_t r; asm("fma.rn.f32x2 %0, %1, %2, %3;" : "=l"(r) : "l"(a), "l"(b), "l"(c)); return r;
}

// complex butterfly: (a,b) -> (a+b, a-b)
__device__ __forceinline__ void bfly(float& ar, float& ai, float& br, float& bi) {
    float sr = fadd1(ar, br), si = fadd1(ai, bi);
    float dr = fsub1(ar, br), di = fsub1(ai, bi);
    ar = sr; ai = si; br = dr; bi = di;
}
// multiply by e^{-2*pi*i*K/16}
template<int K> __device__ __forceinline__ void twf(float& re, float& im) {
    constexpr int k = ((K) % 16 + 16) % 16;
    if constexpr (k == 0) { }
    else if constexpr (k == 4)  { float t = re; re = im;  im = -t; }
    else if constexpr (k == 8)  { re = -re; im = -im; }
    else if constexpr (k == 12) { float t = re; re = -im; im = t;  }
    else {
        constexpr float cs = C16(k), sn = S16(k);
        float nr = fmaf(im,  sn, re * cs);
        float ni = fmaf(re, -sn, im * cs);
        re = nr; im = ni;
    }
}
// multiply by e^{+2*pi*i*K/16}
template<int K> __device__ __forceinline__ void twi(float& re, float& im) {
    constexpr int k = ((K) % 16 + 16) % 16;
    if constexpr (k == 0) { }
    else if constexpr (k == 4)  { float t = re; re = -im; im = t;  }
    else if constexpr (k == 8)  { re = -re; im = -im; }
    else if constexpr (k == 12) { float t = re; re = im;  im = -t; }
    else {
        constexpr float cs = C16(k), sn = S16(k);
        float nr = fmaf(im, -sn, re * cs);
        float ni = fmaf(re,  sn, im * cs);
        re = nr; im = ni;
    }
}

// 16-pt DIF forward FFT, natural in -> bit-reversed out
__device__ __forceinline__ void fft16_fwd(float* Xr, float* Xi) {
#pragma unroll
    for (int j = 0; j < 8; j++) { bfly(Xr[j], Xi[j], Xr[j+8], Xi[j+8]); }
    twf<1>(Xr[9],Xi[9]);  twf<2>(Xr[10],Xi[10]); twf<3>(Xr[11],Xi[11]);
    twf<4>(Xr[12],Xi[12]); twf<5>(Xr[13],Xi[13]); twf<6>(Xr[14],Xi[14]); twf<7>(Xr[15],Xi[15]);
#pragma unroll
    for (int h = 0; h < 2; h++) {
        int o = h * 8;
#pragma unroll
        for (int j = 0; j < 4; j++) bfly(Xr[o+j], Xi[o+j], Xr[o+j+4], Xi[o+j+4]);
        twf<2>(Xr[o+5],Xi[o+5]); twf<4>(Xr[o+6],Xi[o+6]); twf<6>(Xr[o+7],Xi[o+7]);
    }
#pragma unroll
    for (int q = 0; q < 4; q++) {
        int o = q * 4;
        bfly(Xr[o], Xi[o], Xr[o+2], Xi[o+2]);
        bfly(Xr[o+1], Xi[o+1], Xr[o+3], Xi[o+3]);
        twf<4>(Xr[o+3], Xi[o+3]);
    }
#pragma unroll
    for (int p = 0; p < 8; p++) bfly(Xr[2*p], Xi[2*p], Xr[2*p+1], Xi[2*p+1]);
}

// 16-pt DIT inverse FFT (unscaled), bit-reversed in -> natural out
__device__ __forceinline__ void fft16_inv(float* Xr, float* Xi) {
#pragma unroll
    for (int p = 0; p < 8; p++) bfly(Xr[2*p], Xi[2*p], Xr[2*p+1], Xi[2*p+1]);
#pragma unroll
    for (int q = 0; q < 4; q++) {
        int o = q * 4;
        twi<4>(Xr[o+3], Xi[o+3]);
        bfly(Xr[o], Xi[o], Xr[o+2], Xi[o+2]);
        bfly(Xr[o+1], Xi[o+1], Xr[o+3], Xi[o+3]);
    }
#pragma unroll
    for (int h = 0; h < 2; h++) {
        int o = h * 8;
        twi<2>(Xr[o+5],Xi[o+5]); twi<4>(Xr[o+6],Xi[o+6]); twi<6>(Xr[o+7],Xi[o+7]);
#pragma unroll
        for (int j = 0; j < 4; j++) bfly(Xr[o+j], Xi[o+j], Xr[o+j+4], Xi[o+j+4]);
    }
    twi<1>(Xr[9],Xi[9]);  twi<2>(Xr[10],Xi[10]); twi<3>(Xr[11],Xi[11]);
    twi<4>(Xr[12],Xi[12]); twi<5>(Xr[13],Xi[13]); twi<6>(Xr[14],Xi[14]); twi<7>(Xr[15],Xi[15]);
#pragma unroll
    for (int j = 0; j < 8; j++) bfly(Xr[j], Xi[j], Xr[j+8], Xi[j+8]);
}

// ---------------------------------------------------------------------------
// K1 prep: spatial taps for v in {0,8} only (1536 threads, register IFFT)
// ---------------------------------------------------------------------------
__global__ void gf_prep(const float* __restrict__ w) {
    int tid = blockIdx.x * blockDim.x + threadIdx.x;
    if (tid >= CCH * 2) return;
    int vsel = tid & 1;                 // 0 -> v=0, 1 -> v=8
    int c    = tid >> 1;
    int v    = vsel ? 8 : 0;
    float Zr[16], Zi[16];
#pragma unroll
    for (int u = 0; u < 16; u++) {
        int iw = ((u * NV + v) * CCH + c) * 2;
        int i  = REV4(u);
        Zr[i] = w[iw];
        Zi[i] = w[iw + 1];
    }
    fft16_inv(Zr, Zi);                  // y[d] = sum_u W[u] e^{+2 pi i u d/16}
    int ct = c >> 5;
    int cl = c & (CT - 1);
#pragma unroll
    for (int d = 0; d < 16; d++) {
        float* dst = &g_muR[(ct * PP + d) * CT + cl].x;
        dst[vsel] = Zr[d] * (1.0f / 256.0f);
    }
}

// ---------------------------------------------------------------------------
// K2: block 256 thr, grid (24 c-tiles, 32 batch-quads), 4 batches per block.
// All per-thread filter state (raw W / muR taps) loaded into registers once
// per block, before the batch loop.
// ---------------------------------------------------------------------------
__global__ void __launch_bounds__(256, 3) gf_main(const float* __restrict__ x,
                                                  const float* __restrict__ w,
                                                  float* __restrict__ out) {
    __shared__ float2 spec[NV * PP * CT];   // [v][p][c32], reused in-place

    int tid = threadIdx.x;
    int c   = tid & (CT - 1);
    int r   = tid >> 5;                     // 0..7
    int c0  = blockIdx.x * CT;
    int cc  = c;
    int vg  = r;                            // 0 -> packed real (v0,v8); 1..7 -> FFT conv

    // ---- per-block filter preload (registers, reused across BPB batches) ----
    uint64_t muA[16];                       // vg == 0
    float Wr[16], Wi[16];                   // vg != 0 (scaled by 1/128)
    if (vg == 0) {
        const uint64_t* mR = reinterpret_cast<const uint64_t*>(g_muR)
                           + (blockIdx.x * PP) * CT + cc;
#pragma unroll
        for (int d = 0; d < 16; d++) muA[d] = mR[d * CT];
    } else {
        const float2* wb = reinterpret_cast<const float2*>(w) + vg * CCH + c0 + cc;
#pragma unroll
        for (int i = 0; i < 16; i++) {
            float2 t = wb[REV4(i) * NV * CCH];
            Wr[i] = t.x * (1.0f / 128.0f);
            Wi[i] = t.y * (1.0f / 128.0f);
        }
    }

#pragma unroll 1
    for (int bi = 0; bi < BPB; bi++) {
        int b = blockIdx.y * BPB + bi;

        // ---- Phase 1: column rDFT over t, radix-2 folded, rows r and r+8 ----
#pragma unroll
        for (int row = 0; row < 2; row++) {
            int rr = r + row * 8;
            float xr[16];
            const float* xp = x + ((size_t)(b * 256 + rr * 16) * CCH + c0 + c);
#pragma unroll
            for (int t = 0; t < 16; t++) xr[t] = xp[(size_t)t * CCH];

            float s[8], dd[8];
#pragma unroll
            for (int t = 0; t < 8; t++) { s[t] = fadd1(xr[t], xr[t+8]); dd[t] = fsub1(xr[t], xr[t+8]); }
            {
                float a = fadd1(fadd1(s[0], s[1]), fadd1(s[2], s[3]));
                float bb= fadd1(fadd1(s[4], s[5]), fadd1(s[6], s[7]));
                spec[(0 * PP + rr) * CT + c].x = fadd1(a, bb);
            }
            {
                float a = fadd1(fsub1(s[0], s[1]), fsub1(s[2], s[3]));
                float bb= fadd1(fsub1(s[4], s[5]), fsub1(s[6], s[7]));
                spec[(8 * PP + rr) * CT + c].x = fadd1(a, bb);
            }
#pragma unroll
            for (int v = 1; v < 8; v++) {
                const float* src = (v & 1) ? dd : s;
                float re = 0.0f, im = 0.0f;
#pragma unroll
                for (int t = 0; t < 8; t++) {
                    re = fmaf(src[t],  C16(v * t), re);
                    im = fmaf(src[t], -S16(v * t), im);
                }
                spec[(v * PP + rr) * CT + c] = make_float2(re, im);
            }
        }
        __syncthreads();

        // ---- Phase 2 ----
        if (vg == 0) {
            // packed real dense conv for v=0 (lo) and v=8 (hi),
            // two halves of 8 outputs; results written into .y slots.
#pragma unroll
            for (int half = 0; half < 2; half++) {
                uint64_t T[8];
#pragma unroll
                for (int s8 = 0; s8 < 8; s8++) T[s8] = pack2(0.0f, 0.0f);
#pragma unroll
                for (int p = 0; p < 16; p++) {
                    float x0 = spec[(0 * PP + p) * CT + cc].x;
                    float x8 = spec[(8 * PP + p) * CT + cc].x;
                    uint64_t XR = pack2(x0, x8);
#pragma unroll
                    for (int s8 = 0; s8 < 8; s8++) {
                        int s = half * 8 + s8;
                        T[s8] = fma2(muA[(s - p) & 15], XR, T[s8]);
                    }
                }
#pragma unroll
                for (int s8 = 0; s8 < 8; s8++) {
                    int s = half * 8 + s8;
                    float t0, t8;
                    unpack2(T[s8], t0, t8);
                    spec[(0 * PP + s) * CT + cc].y = t0;
                    spec[(8 * PP + s) * CT + cc].y = t8;
                }
            }
        } else {
            int v = vg;
            float Xr[16], Xi[16];
#pragma unroll
            for (int p = 0; p < 16; p++) {
                float2 t = spec[(v * PP + p) * CT + cc];
                Xr[p] = t.x; Xi[p] = t.y;
            }
            fft16_fwd(Xr, Xi);
#pragma unroll
            for (int i = 0; i < 16; i++) {
                float nr = fmaf(-Xi[i], Wi[i], Xr[i] * Wr[i]);
                float ni = fmaf( Xi[i], Wr[i], Xr[i] * Wi[i]);
                Xr[i] = nr; Xi[i] = ni;
            }
            fft16_inv(Xr, Xi);
#pragma unroll
            for (int s = 0; s < 16; s++)
                spec[(v * PP + s) * CT + cc] = make_float2(Xr[s], Xi[s]);
        }
        __syncthreads();

        // ---- Phase 3: inverse column pass, radix-2 folded ----
        // v0/v8 results live in the .y slots; v=1..7 are full complex.
#pragma unroll
        for (int row = 0; row < 2; row++) {
            int rr = r + row * 8;
            float tv0 = spec[(0 * PP + rr) * CT + c].y;
            float tv8 = spec[(8 * PP + rr) * CT + c].y;
            float2 Tv[8];
#pragma unroll
            for (int v = 1; v < 8; v++) Tv[v] = spec[(v * PP + rr) * CT + c];

            float* op = out + ((size_t)(b * 256 + rr * 16) * CCH + c0 + c);
#pragma unroll
            for (int t = 0; t < 8; t++) {
                float ge = tv0;
                ge = fmaf(tv8, C16(8 * t), ge);
#pragma unroll
                for (int v = 2; v < 8; v += 2) {
                    ge = fmaf(Tv[v].x,  C16(v * t), ge);
                    ge = fmaf(Tv[v].y, -S16(v * t), ge);
                }
                float go = 0.0f;
#pragma unroll
                for (int v = 1; v < 8; v += 2) {
                    go = fmaf(Tv[v].x,  C16(v * t), go);
                    go = fmaf(Tv[v].y, -S16(v * t), go);
                }
                op[(size_t)t * CCH]       = fadd1(ge, go);
                op[(size_t)(t + 8) * CCH] = fsub1(ge, go);
            }
        }
        __syncthreads();   // spec reused by next batch's phase 1
    }
}

// ---------------------------------------------------------------------------
extern "C" void kernel_launch(void* const* d_in, const int* in_sizes, int n_in,
                              void* d_out, int out_size) {
    const float* x = (const float*)d_in[0];
    const float* w = (const float*)d_in[1];
    float* out     = (float*)d_out;
    (void)in_sizes; (void)n_in; (void)out_size;

    gf_prep<<<(CCH * 2 + 255) / 256, 256>>>(w);

    dim3 grid(NCT, 128 / BPB);
    gf_main<<<grid, 256>>>(x, w, out);
}

// round 13
// speedup vs baseline: 1.1137x; 1.1137x over previous
#include <cuda_runtime.h>
#include <cstdint>

// GlobalFilter: out = irfft2( rfft2(x,ortho) * W, ortho ), 16x16 spatial, per channel.
//   Ph1: column rDFT over t (radix-2 folded)                 thread=(c32, 2 rows)
//   Ph2: per-(c,v) row circular conv via 16-pt FFT +
//        pointwise W-multiply + IFFT  (v=1..7 complex;
//        v={0,8} packed real dense conv)
//   Ph3: inverse column pass (radix-2 folded)                thread=(c32, 2 rows)
//
// x: [128,256,768] f32 ; W: [16,9,768,2] f32 ; out: [128,256,768] f32

#define PP    16
#define NV    9
#define CT    32
#define CCH   768
#define NCT   (CCH / CT)   // 24

// real taps for v=0 / v=8 dense conv: [ct][d][c32] -> (mu0, mu8)*1/256
__device__ float2 g_muR[NCT * PP * CT];
// freq-domain filter for v=1..7, BIT-REVERSED u order, scale 1/128:
// [ct][v-1][i][c32] -> (re, im)
__device__ float2 g_Wh[NCT * 7 * PP * CT];

__host__ __device__ __forceinline__ constexpr float C16(int k) {
    return (k % 16 == 0)  ?  1.0f :
           (k % 16 == 1)  ?  0.9238795325112867f :
           (k % 16 == 2)  ?  0.7071067811865476f :
           (k % 16 == 3)  ?  0.3826834323650898f :
           (k % 16 == 4)  ?  0.0f :
           (k % 16 == 5)  ? -0.3826834323650898f :
           (k % 16 == 6)  ? -0.7071067811865476f :
           (k % 16 == 7)  ? -0.9238795325112867f :
           (k % 16 == 8)  ? -1.0f :
           (k % 16 == 9)  ? -0.9238795325112867f :
           (k % 16 == 10) ? -0.7071067811865476f :
           (k % 16 == 11) ? -0.3826834323650898f :
           (k % 16 == 12) ?  0.0f :
           (k % 16 == 13) ?  0.3826834323650898f :
           (k % 16 == 14) ?  0.7071067811865476f :
                             0.9238795325112867f;
}
__host__ __device__ __forceinline__ constexpr float S16(int k) {
    return C16(k % 16 + 12);
}
__host__ __device__ __forceinline__ constexpr int REV4(int i) {
    return ((i & 1) << 3) | ((i & 2) << 1) | ((i & 4) >> 1) | ((i & 8) >> 3);
}

// a+b / a-b as FFMA-imm (rt=1 vs rt=2 for FADD)
__device__ __forceinline__ float fadd1(float a, float b) {
    float r; asm("fma.rn.f32 %0, %1, 0f3F800000, %2;" : "=f"(r) : "f"(a), "f"(b)); return r;
}
__device__ __forceinline__ float fsub1(float a, float b) {  // a - b
    float r; asm("fma.rn.f32 %0, %1, 0fBF800000, %2;" : "=f"(r) : "f"(b), "f"(a)); return r;
}

__device__ __forceinline__ uint64_t pack2(float lo, float hi) {
    uint64_t r; asm("mov.b64 %0, {%1, %2};" : "=l"(r) : "f"(lo), "f"(hi)); return r;
}
__device__ __forceinline__ void unpack2(uint64_t v, float& lo, float& hi) {
    asm("mov.b64 {%0, %1}, %2;" : "=f"(lo), "=f"(hi) : "l"(v));
}
__device__ __forceinline__ uint64_t fma2(uint64_t a, uint64_t b, uint64_t c) {
    uint64_t r; asm("fma.rn.f32x2 %0, %1, %2, %3;" : "=l"(r) : "l"(a), "l"(b), "l"(c)); return r;
}

// complex butterfly: (a,b) -> (a+b, a-b)
__device__ __forceinline__ void bfly(float& ar, float& ai, float& br, float& bi) {
    float sr = fadd1(ar, br), si = fadd1(ai, bi);
    float dr = fsub1(ar, br), di = fsub1(ai, bi);
    ar = sr; ai = si; br = dr; bi = di;
}
// multiply by e^{-2*pi*i*K/16}
template<int K> __device__ __forceinline__ void twf(float& re, float& im) {
    constexpr int k = ((K) % 16 + 16) % 16;
    if constexpr (k == 0) { }
    else if constexpr (k == 4)  { float t = re; re = im;  im = -t; }
    else if constexpr (k == 8)  { re = -re; im = -im; }
    else if constexpr (k == 12) { float t = re; re = -im; im = t;  }
    else {
        constexpr float cs = C16(k), sn = S16(k);
        float nr = fmaf(im,  sn, re * cs);
        float ni = fmaf(re, -sn, im * cs);
        re = nr; im = ni;
    }
}
// multiply by e^{+2*pi*i*K/16}
template<int K> __device__ __forceinline__ void twi(float& re, float& im) {
    constexpr int k = ((K) % 16 + 16) % 16;
    if constexpr (k == 0) { }
    else if constexpr (k == 4)  { float t = re; re = -im; im = t;  }
    else if constexpr (k == 8)  { re = -re; im = -im; }
    else if constexpr (k == 12) { float t = re; re = im;  im = -t; }
    else {
        constexpr float cs = C16(k), sn = S16(k);
        float nr = fmaf(im, -sn, re * cs);
        float ni = fmaf(re,  sn, im * cs);
        re = nr; im = ni;
    }
}

// 16-pt DIF forward FFT, natural in -> bit-reversed out
__device__ __forceinline__ void fft16_fwd(float* Xr, float* Xi) {
#pragma unroll
    for (int j = 0; j < 8; j++) { bfly(Xr[j], Xi[j], Xr[j+8], Xi[j+8]); }
    twf<1>(Xr[9],Xi[9]);  twf<2>(Xr[10],Xi[10]); twf<3>(Xr[11],Xi[11]);
    twf<4>(Xr[12],Xi[12]); twf<5>(Xr[13],Xi[13]); twf<6>(Xr[14],Xi[14]); twf<7>(Xr[15],Xi[15]);
#pragma unroll
    for (int h = 0; h < 2; h++) {
        int o = h * 8;
#pragma unroll
        for (int j = 0; j < 4; j++) bfly(Xr[o+j], Xi[o+j], Xr[o+j+4], Xi[o+j+4]);
        twf<2>(Xr[o+5],Xi[o+5]); twf<4>(Xr[o+6],Xi[o+6]); twf<6>(Xr[o+7],Xi[o+7]);
    }
#pragma unroll
    for (int q = 0; q < 4; q++) {
        int o = q * 4;
        bfly(Xr[o], Xi[o], Xr[o+2], Xi[o+2]);
        bfly(Xr[o+1], Xi[o+1], Xr[o+3], Xi[o+3]);
        twf<4>(Xr[o+3], Xi[o+3]);
    }
#pragma unroll
    for (int p = 0; p < 8; p++) bfly(Xr[2*p], Xi[2*p], Xr[2*p+1], Xi[2*p+1]);
}

// 16-pt DIT inverse FFT (unscaled), bit-reversed in -> natural out
__device__ __forceinline__ void fft16_inv(float* Xr, float* Xi) {
#pragma unroll
    for (int p = 0; p < 8; p++) bfly(Xr[2*p], Xi[2*p], Xr[2*p+1], Xi[2*p+1]);
#pragma unroll
    for (int q = 0; q < 4; q++) {
        int o = q * 4;
        twi<4>(Xr[o+3], Xi[o+3]);
        bfly(Xr[o], Xi[o], Xr[o+2], Xi[o+2]);
        bfly(Xr[o+1], Xi[o+1], Xr[o+3], Xi[o+3]);
    }
#pragma unroll
    for (int h = 0; h < 2; h++) {
        int o = h * 8;
        twi<2>(Xr[o+5],Xi[o+5]); twi<4>(Xr[o+6],Xi[o+6]); twi<6>(Xr[o+7],Xi[o+7]);
#pragma unroll
        for (int j = 0; j < 4; j++) bfly(Xr[o+j], Xi[o+j], Xr[o+j+4], Xi[o+j+4]);
    }
    twi<1>(Xr[9],Xi[9]);  twi<2>(Xr[10],Xi[10]); twi<3>(Xr[11],Xi[11]);
    twi<4>(Xr[12],Xi[12]); twi<5>(Xr[13],Xi[13]); twi<6>(Xr[14],Xi[14]); twi<7>(Xr[15],Xi[15]);
#pragma unroll
    for (int j = 0; j < 8; j++) bfly(Xr[j], Xi[j], Xr[j+8], Xi[j+8]);
}

// ---------------------------------------------------------------------------
// K1 prep (single kernel, no trig tables):
//   tid <  86016 : scaled copy of W (v=1..7) into bit-reversed g_Wh
//   tid >= 86016 : register IFFT to build spatial taps muR for v in {0,8}
// ---------------------------------------------------------------------------
#define T_COPY (NCT * 7 * PP * CT)   // 86016
#define T_TAPS (CCH * 2)             // 1536

__global__ void gf_prep(const float* __restrict__ w) {
    int tid = blockIdx.x * blockDim.x + threadIdx.x;
    if (tid < T_COPY) {
        int cl   = tid & (CT - 1);
        int rest = tid >> 5;
        int u    = rest & 15;
        int rest2= rest >> 4;
        int vm1  = rest2 % 7;
        int ct   = rest2 / 7;
        int c    = ct * CT + cl;
        int v    = vm1 + 1;
        int iw   = ((u * NV + v) * CCH + c) * 2;
        g_Wh[((ct * 7 + vm1) * PP + REV4(u)) * CT + cl] =
            make_float2(w[iw] * (1.0f / 128.0f), w[iw + 1] * (1.0f / 128.0f));
    } else if (tid < T_COPY + T_TAPS) {
        int t2   = tid - T_COPY;
        int vsel = t2 & 1;              // 0 -> v=0, 1 -> v=8
        int c    = t2 >> 1;
        int v    = vsel ? 8 : 0;
        float Zr[16], Zi[16];
#pragma unroll
        for (int u = 0; u < 16; u++) {
            int iw = ((u * NV + v) * CCH + c) * 2;
            int i  = REV4(u);
            Zr[i] = w[iw];
            Zi[i] = w[iw + 1];
        }
        fft16_inv(Zr, Zi);              // y[d] = sum_u W[u] e^{+2 pi i u d/16}
        int ct = c >> 5;
        int cl = c & (CT - 1);
#pragma unroll
        for (int d = 0; d < 16; d++) {
            float* dst = &g_muR[(ct * PP + d) * CT + cl].x;
            dst[vsel] = Zr[d] * (1.0f / 256.0f);
        }
    }
}

// ---------------------------------------------------------------------------
// K2: block 256 thr, grid (24 c-tiles, 64 batch-pairs), 2 batches per block
// (R4 configuration: per-block register preload of filter state)
// ---------------------------------------------------------------------------
__global__ void __launch_bounds__(256, 3) gf_main(const float* __restrict__ x,
                                                  float* __restrict__ out) {
    __shared__ float2 spec[NV * PP * CT];   // [v][p][c32], reused in-place

    int tid = threadIdx.x;
    int c   = tid & (CT - 1);
    int r   = tid >> 5;                     // 0..7
    int c0  = blockIdx.x * CT;
    int cc  = c;
    int vg  = r;                            // 0 -> packed real (v0,v8); 1..7 -> FFT conv

    // --- preload per-thread filter data (reused for both batches) ---
    uint64_t muA[16];                       // vg==0 only
    float Whr[16], Whi[16];                 // vg!=0 only
    if (vg == 0) {
        const uint64_t* mR = reinterpret_cast<const uint64_t*>(g_muR)
                           + (blockIdx.x * PP) * CT + cc;
#pragma unroll
        for (int d = 0; d < 16; d++) muA[d] = mR[d * CT];
    } else {
        const float2* wh = g_Wh + ((blockIdx.x * 7 + vg - 1) * PP) * CT + cc;
#pragma unroll
        for (int i = 0; i < 16; i++) { float2 t = wh[i * CT]; Whr[i] = t.x; Whi[i] = t.y; }
    }

    for (int bi = 0; bi < 2; bi++) {
        int b = blockIdx.y * 2 + bi;

        // ---- Phase 1: column rDFT over t, radix-2 folded, rows r and r+8 ----
#pragma unroll
        for (int row = 0; row < 2; row++) {
            int rr = r + row * 8;
            float xr[16];
            const float* xp = x + ((size_t)(b * 256 + rr * 16) * CCH + c0 + c);
#pragma unroll
            for (int t = 0; t < 16; t++) xr[t] = xp[(size_t)t * CCH];

            float s[8], dd[8];
#pragma unroll
            for (int t = 0; t < 8; t++) { s[t] = fadd1(xr[t], xr[t+8]); dd[t] = fsub1(xr[t], xr[t+8]); }
            {
                float a = fadd1(fadd1(s[0], s[1]), fadd1(s[2], s[3]));
                float bb= fadd1(fadd1(s[4], s[5]), fadd1(s[6], s[7]));
                spec[(0 * PP + rr) * CT + c] = make_float2(fadd1(a, bb), 0.0f);
            }
            {
                float a = fadd1(fsub1(s[0], s[1]), fsub1(s[2], s[3]));
                float bb= fadd1(fsub1(s[4], s[5]), fsub1(s[6], s[7]));
                spec[(8 * PP + rr) * CT + c] = make_float2(fadd1(a, bb), 0.0f);
            }
#pragma unroll
            for (int v = 1; v < 8; v++) {
                const float* src = (v & 1) ? dd : s;
                float re = 0.0f, im = 0.0f;
#pragma unroll
                for (int t = 0; t < 8; t++) {
                    re = fmaf(src[t],  C16(v * t), re);
                    im = fmaf(src[t], -S16(v * t), im);
                }
                spec[(v * PP + rr) * CT + c] = make_float2(re, im);
            }
        }
        __syncthreads();

        // ---- Phase 2 ----
        if (vg == 0) {
            // packed real dense conv for v=0 (lane lo) and v=8 (lane hi)
            uint64_t T[16];
#pragma unroll
            for (int s = 0; s < 16; s++) T[s] = pack2(0.0f, 0.0f);
#pragma unroll
            for (int p = 0; p < 16; p++) {
                float x0 = spec[(0 * PP + p) * CT + cc].x;
                float x8 = spec[(8 * PP + p) * CT + cc].x;
                uint64_t XR = pack2(x0, x8);
#pragma unroll
                for (int s = 0; s < 16; s++)
                    T[s] = fma2(muA[(s - p) & 15], XR, T[s]);
            }
#pragma unroll
            for (int s = 0; s < 16; s++) {
                float t0, t8;
                unpack2(T[s], t0, t8);
                spec[(0 * PP + s) * CT + cc] = make_float2(t0, 0.0f);
                spec[(8 * PP + s) * CT + cc] = make_float2(t8, 0.0f);
            }
        } else {
            int v = vg;
            float Xr[16], Xi[16];
#pragma unroll
            for (int p = 0; p < 16; p++) {
                float2 t = spec[(v * PP + p) * CT + cc];
                Xr[p] = t.x; Xi[p] = t.y;
            }
            fft16_fwd(Xr, Xi);
#pragma unroll
            for (int i = 0; i < 16; i++) {
                float nr = fmaf(-Xi[i], Whi[i], Xr[i] * Whr[i]);
                float ni = fmaf( Xi[i], Whr[i], Xr[i] * Whi[i]);
                Xr[i] = nr; Xi[i] = ni;
            }
            fft16_inv(Xr, Xi);
#pragma unroll
            for (int s = 0; s < 16; s++)
                spec[(v * PP + s) * CT + cc] = make_float2(Xr[s], Xi[s]);
        }
        __syncthreads();

        // ---- Phase 3: inverse column pass, radix-2 folded ----
#pragma unroll
        for (int row = 0; row < 2; row++) {
            int rr = r + row * 8;
            float2 Tv[NV];
#pragma unroll
            for (int v = 0; v < NV; v++) Tv[v] = spec[(v * PP + rr) * CT + c];

            float* op = out + ((size_t)(b * 256 + rr * 16) * CCH + c0 + c);
#pragma unroll
            for (int t = 0; t < 8; t++) {
                float ge = Tv[0].x;
                ge = fmaf(Tv[8].x, C16(8 * t), ge);
#pragma unroll
                for (int v = 2; v < 8; v += 2) {
                    ge = fmaf(Tv[v].x,  C16(v * t), ge);
                    ge = fmaf(Tv[v].y, -S16(v * t), ge);
                }
                float go = 0.0f;
#pragma unroll
                for (int v = 1; v < 8; v += 2) {
                    go = fmaf(Tv[v].x,  C16(v * t), go);
                    go = fmaf(Tv[v].y, -S16(v * t), go);
                }
                op[(size_t)t * CCH]       = fadd1(ge, go);
                op[(size_t)(t + 8) * CCH] = fsub1(ge, go);
            }
        }
        __syncthreads();   // spec reused by next batch's phase 1
    }
}

// ---------------------------------------------------------------------------
extern "C" void kernel_launch(void* const* d_in, const int* in_sizes, int n_in,
                              void* d_out, int out_size) {
    const float* x = (const float*)d_in[0];
    const float* w = (const float*)d_in[1];
    float* out     = (float*)d_out;
    (void)in_sizes; (void)n_in; (void)out_size;

    gf_prep<<<(T_COPY + T_TAPS + 255) / 256, 256>>>(w);

    dim3 grid(NCT, 64);
    gf_main<<<grid, 256>>>(x, out);
}